// round 7
// baseline (speedup 1.0000x reference)
#include <cuda_runtime.h>
#include <cstdint>

#define WIDTH  1024
#define HALF   512
#define DEPTH  8
#define BDEPTH 10
#define BATCH  65536

typedef unsigned long long ull;

// Geometry:
//   lane = p bits [6:2]  (32 lanes)
//   slot v (0..31): p = ((v>>2)<<7) | (lane<<2) | (v&3)   -> v bits = p bits {1,0,9,8,7}
//   thread holds val[v*2+h]: h=0 rows(0,1), h=1 rows(2,3) packed in f32x2.
// Steps t (bit b = 9-t): t=0,1,2 reg (v bits 4,3,2); t=3..7 lane (lane bits 4..0);
//                        t=8,9 reg (v bits 1,0).
//
// g_bt (steps t=1..9): 256 float4 per step, LDG.128:
//   reg step:  entry[e*32 + lane], e=0..7:  (c[pi=2e], s[2e], c[2e+1], s[2e+1])
//   lane step: entry[e*16 + lp],  e=0..15: (c[v=2e],  s[2e], c[2e+1], s[2e+1])
// g_t0 (step t=0, scale-folded): entry[L*512 + pi*32 + lane] = (a, b, -g, d)
//   where n0 = a*x0 + b*x1 ; n1 = (-g)*x0 + d*x1, a=c*sc0, b=s*sc1, g=s*sc0, d=c*sc1
//   (sc = previous layer's quintic scale; sc=1 for layer 0).
__device__ float4 g_bt[DEPTH * BDEPTH * 256];
__device__ float4 g_t0[DEPTH * 512];
// quintic (scale-folded out): entry[act*512 + e*32 + lane] = (m_v0, nb_v0, m_v1, nb_v1)
// for v0=2e, v1=2e+1; m=slope/scale, nb=-bias/scale.
__device__ float4 g_qt[(DEPTH - 1) * 512];

// ---------- f32x2 helpers ----------
__device__ __forceinline__ ull pk(float lo, float hi) {
    ull r;
    asm("mov.b64 %0, {%1, %2};" : "=l"(r) : "r"(__float_as_uint(lo)), "r"(__float_as_uint(hi)));
    return r;
}
__device__ __forceinline__ void unpk(ull v, float& lo, float& hi) {
    unsigned a, b;
    asm("mov.b64 {%0, %1}, %2;" : "=r"(a), "=r"(b) : "l"(v));
    lo = __uint_as_float(a);
    hi = __uint_as_float(b);
}
__device__ __forceinline__ ull f2mul(ull a, ull b) {
    ull r;
    asm("mul.rn.f32x2 %0, %1, %2;" : "=l"(r) : "l"(a), "l"(b));
    return r;
}
__device__ __forceinline__ ull f2fma(ull a, ull b, ull c) {
    ull r;
    asm("fma.rn.f32x2 %0, %1, %2, %3;" : "=l"(r) : "l"(a), "l"(b), "l"(c));
    return r;
}
__device__ __forceinline__ void cfence() { asm volatile("" ::: "memory"); }

// ---------- prep ----------
#define BT_ELEMS (DEPTH * BDEPTH * 256)
#define T0_ELEMS (DEPTH * 512)
#define QT_ELEMS ((DEPTH - 1) * 512)

__device__ __forceinline__ float theta_of(const float* bp, int layer, int t, int p0) {
    int j = 0;
#pragma unroll
    for (int k = 0; k < 9; k++) {
        int src = ((k - t) % 10 + 10) % 10;
        j |= ((p0 >> src) & 1) << k;
    }
    return bp[layer * (HALF * BDEPTH) + j * BDEPTH + t];
}

__global__ void prep_all(const float* __restrict__ bp,
                         const float* __restrict__ bias,
                         const float* __restrict__ slope,
                         const float* __restrict__ scale) {
    int e0 = blockIdx.x * blockDim.x + threadIdx.x;
    if (e0 < BT_ELEMS) {
        // steps t=1..9 (t=0 handled by g_t0 below; that region is unused)
        int T = e0 >> 8;
        int idx = e0 & 255;
        int layer = T / BDEPTH;
        int t = T % BDEPTH;
        if (t == 0) return;
        int b = 9 - t;

        float4 out;
        if (b >= 7 || b <= 1) {
            int sbit = (b >= 7) ? (b - 5) : b;
            int m = 1 << sbit;
            int e = idx >> 5;
            int lane = idx & 31;
            float cs[4];
#pragma unroll
            for (int k = 0; k < 2; k++) {
                int pi = 2 * e + k;
                int v0 = (pi & (m - 1)) | ((pi & ~(m - 1)) << 1);
                int p0 = ((v0 >> 2) << 7) | (lane << 2) | (v0 & 3);
                float th = theta_of(bp, layer, t, p0);
                float s, c;
                sincosf(th, &s, &c);
                cs[2 * k] = c;
                cs[2 * k + 1] = s;
            }
            out = make_float4(cs[0], cs[1], cs[2], cs[3]);
        } else {
            int lm = 1 << (b - 2);
            int e = idx >> 4;
            int lp = idx & 15;
            int l0 = (lp & (lm - 1)) | ((lp & ~(lm - 1)) << 1);
            float cs[4];
#pragma unroll
            for (int k = 0; k < 2; k++) {
                int v = 2 * e + k;
                int p0 = ((v >> 2) << 7) | (l0 << 2) | (v & 3);
                float th = theta_of(bp, layer, t, p0);
                float s, c;
                sincosf(th, &s, &c);
                cs[2 * k] = c;
                cs[2 * k + 1] = s;
            }
            out = make_float4(cs[0], cs[1], cs[2], cs[3]);
        }
        g_bt[e0] = out;
    } else if (e0 < BT_ELEMS + T0_ELEMS) {
        // t=0 tables with previous layer's quintic scale folded in
        int q = e0 - BT_ELEMS;
        int layer = q >> 9;
        int idx = q & 511;
        int pi = idx >> 5;          // pair 0..15, v0 = pi, v1 = pi+16 (M=16)
        int lane = idx & 31;
        int v0 = pi, v1 = pi | 16;
        int p0 = ((v0 >> 2) << 7) | (lane << 2) | (v0 & 3);
        int p1 = ((v1 >> 2) << 7) | (lane << 2) | (v1 & 3);
        float th = theta_of(bp, layer, 0, p0);
        float s, c;
        sincosf(th, &s, &c);
        float sc0 = 1.0f, sc1 = 1.0f;
        if (layer > 0) {
            sc0 = scale[(layer - 1) * WIDTH + p0];
            sc1 = scale[(layer - 1) * WIDTH + p1];
        }
        g_t0[q] = make_float4(c * sc0, s * sc1, -s * sc0, c * sc1);
    } else if (e0 < BT_ELEMS + T0_ELEMS + QT_ELEMS) {
        int q = e0 - BT_ELEMS - T0_ELEMS;
        int act = q >> 9;
        int idx = q & 511;
        int e = idx >> 5;           // v0 = 2e, v1 = 2e+1
        int l = idx & 31;
        float mv[2], nbv[2];
#pragma unroll
        for (int k = 0; k < 2; k++) {
            int v = 2 * e + k;
            int p0 = ((v >> 2) << 7) | (l << 2) | (v & 3);
            float bi = bias[act * WIDTH + p0];
            float sl = slope[act * WIDTH + p0];
            float sc = scale[act * WIDTH + p0];
            mv[k] = sl / sc;
            nbv[k] = -bi / sc;
        }
        g_qt[q] = make_float4(mv[0], nbv[0], mv[1], nbv[1]);
    }
}

// ---------- main kernel ----------

__device__ __forceinline__ void bfly_pair(ull (&val)[64], int v0, int v1, float c, float s) {
    ull c2 = pk(c, c);
    ull s2 = pk(s, s);
    ull ns2 = s2 ^ 0x8000000080000000ULL;
#pragma unroll
    for (int h = 0; h < 2; h++) {
        ull x0 = val[v0 * 2 + h];
        ull x1 = val[v1 * 2 + h];
        val[v0 * 2 + h] = f2fma(c2, x0, f2mul(s2, x1));   // n0 =  c*x0 + s*x1
        val[v1 * 2 + h] = f2fma(c2, x1, f2mul(ns2, x0));  // n1 =  c*x1 - s*x0
    }
}

// t=0 with folded scale: n0 = a*x0 + b*x1 ; n1 = g*x0 + d*x1 (g pre-negated)
__device__ __forceinline__ void t0_step(ull (&val)[64], int lane, const float4* __restrict__ t0t) {
#pragma unroll
    for (int pi = 0; pi < 16; pi++) {
        float4 q = __ldg(t0t + pi * 32 + lane);
        ull a2 = pk(q.x, q.x);
        ull b2 = pk(q.y, q.y);
        ull g2 = pk(q.z, q.z);
        ull d2 = pk(q.w, q.w);
        const int v0 = pi, v1 = pi | 16;
#pragma unroll
        for (int h = 0; h < 2; h++) {
            ull x0 = val[v0 * 2 + h];
            ull x1 = val[v1 * 2 + h];
            val[v0 * 2 + h] = f2fma(a2, x0, f2mul(b2, x1));
            val[v1 * 2 + h] = f2fma(g2, x0, f2mul(d2, x1));
        }
        if ((pi & 3) == 3) cfence();
    }
}

template <int M>
__device__ __forceinline__ void reg_step(ull (&val)[64], int lane, const float4* __restrict__ bt) {
#pragma unroll
    for (int e = 0; e < 8; e++) {
        float4 q = __ldg(bt + e * 32 + lane);
        {
            const int pi = 2 * e;
            const int v0 = (pi & (M - 1)) | ((pi & ~(M - 1)) << 1);
            bfly_pair(val, v0, v0 | M, q.x, q.y);
        }
        {
            const int pi = 2 * e + 1;
            const int v0 = (pi & (M - 1)) | ((pi & ~(M - 1)) << 1);
            bfly_pair(val, v0, v0 | M, q.z, q.w);
        }
        if (e & 1) cfence();
    }
}

template <int LM>
__device__ __forceinline__ void lane_step(ull (&val)[64], int lane, const float4* __restrict__ bt) {
    const ull smask = (lane & LM) ? 0x8000000080000000ULL : 0ULL;
    const int lp = (lane & (LM - 1)) | ((lane >> 1) & ~(LM - 1));
#pragma unroll
    for (int e = 0; e < 16; e++) {
        float4 q = __ldg(bt + e * 16 + lp);
#pragma unroll
        for (int k = 0; k < 2; k++) {
            const int v = 2 * e + k;
            float c = k ? q.z : q.x;
            float s = k ? q.w : q.y;
            ull c2 = pk(c, c);
            ull s2 = pk(s, s) ^ smask;
#pragma unroll
            for (int h = 0; h < 2; h++) {
                ull x = val[v * 2 + h];
                ull xp = __shfl_xor_sync(0xffffffffu, x, LM);
                val[v * 2 + h] = f2fma(c2, x, f2mul(s2, xp));
            }
        }
        if (e & 1) cfence();
    }
}

// quintic WITHOUT trailing scale (folded into next layer's t0)
__device__ __forceinline__ void quintic(ull (&val)[64], int lane, int act) {
    const float4* __restrict__ qt = g_qt + act * 512;
    const ull C1875 = 0x3FF000003FF00000ULL;  // (1.875, 1.875)
    const ull CM125 = 0xBFA00000BFA00000ULL;  // (-1.25, -1.25)
    const ull C0375 = 0x3EC000003EC00000ULL;  // (0.375, 0.375)
#pragma unroll
    for (int e = 0; e < 16; e++) {
        float4 q = __ldg(qt + e * 32 + lane);
#pragma unroll
        for (int k = 0; k < 2; k++) {
            const int v = 2 * e + k;
            ull m2 = pk(k ? q.z : q.x, k ? q.z : q.x);
            ull nb2 = pk(k ? q.w : q.y, k ? q.w : q.y);
#pragma unroll
            for (int h = 0; h < 2; h++) {
                ull u = f2fma(val[v * 2 + h], m2, nb2);
                float lo, hi;
                unpk(u, lo, hi);
                lo = fminf(fmaxf(lo, -1.0f), 1.0f);
                hi = fminf(fmaxf(hi, -1.0f), 1.0f);
                u = pk(lo, hi);
                ull u2 = f2mul(u, u);
                ull p = f2fma(u2, C0375, CM125);
                p = f2fma(u2, p, C1875);
                val[v * 2 + h] = f2mul(u, p);
            }
        }
        if (e & 3) cfence();
    }
}

__global__ void __launch_bounds__(128, 3)
net_kernel(const float* __restrict__ X, float* __restrict__ Y) {
    const int lane = threadIdx.x & 31;
    const int w = blockIdx.x * 4 + (threadIdx.x >> 5);
    const long long row0 = (long long)w * 4;
    const float* __restrict__ xr0 = X + row0 * WIDTH;
    const float* __restrict__ xr1 = xr0 + WIDTH;
    const float* __restrict__ xr2 = xr1 + WIDTH;
    const float* __restrict__ xr3 = xr2 + WIDTH;

    ull val[64];

    // load: 4 rows; val[v*2+h]: h=0 -> (row0,row1), h=1 -> (row2,row3)
#pragma unroll
    for (int vhi = 0; vhi < 8; vhi++) {
        int off = vhi * 128 + lane * 4;
        int s = vhi * 4;
        {
            float4 a = *(const float4*)(xr0 + off);
            float4 b = *(const float4*)(xr1 + off);
            val[(s + 0) * 2 + 0] = pk(a.x, b.x);
            val[(s + 1) * 2 + 0] = pk(a.y, b.y);
            val[(s + 2) * 2 + 0] = pk(a.z, b.z);
            val[(s + 3) * 2 + 0] = pk(a.w, b.w);
        }
        cfence();
        {
            float4 c = *(const float4*)(xr2 + off);
            float4 d = *(const float4*)(xr3 + off);
            val[(s + 0) * 2 + 1] = pk(c.x, d.x);
            val[(s + 1) * 2 + 1] = pk(c.y, d.y);
            val[(s + 2) * 2 + 1] = pk(c.z, d.z);
            val[(s + 3) * 2 + 1] = pk(c.w, d.w);
        }
        cfence();
    }

#pragma unroll 1
    for (int layer = 0; layer < DEPTH; layer++) {
        const float4* __restrict__ bt = g_bt + layer * (BDEPTH * 256);
        t0_step(val, lane, g_t0 + layer * 512);  // t=0: p bit 9, scale-folded
        reg_step<8>(val, lane, bt + 1 * 256);    // t=1: p bit 8 (v bit 3)
        reg_step<4>(val, lane, bt + 2 * 256);    // t=2: p bit 7 (v bit 2)
        lane_step<16>(val, lane, bt + 3 * 256);  // t=3: p bit 6 (lane bit 4)
        lane_step<8>(val, lane, bt + 4 * 256);   // t=4: p bit 5
        lane_step<4>(val, lane, bt + 5 * 256);   // t=5: p bit 4
        lane_step<2>(val, lane, bt + 6 * 256);   // t=6: p bit 3
        lane_step<1>(val, lane, bt + 7 * 256);   // t=7: p bit 2 (lane bit 0)
        reg_step<2>(val, lane, bt + 8 * 256);    // t=8: p bit 1 (v bit 1)
        reg_step<1>(val, lane, bt + 9 * 256);    // t=9: p bit 0 (v bit 0)
        if (layer < DEPTH - 1) quintic(val, lane, layer);
    }

    // store (net permutation over 10 steps per layer is identity)
    float* __restrict__ yr0 = Y + row0 * WIDTH;
    float* __restrict__ yr1 = yr0 + WIDTH;
    float* __restrict__ yr2 = yr1 + WIDTH;
    float* __restrict__ yr3 = yr2 + WIDTH;
#pragma unroll
    for (int vhi = 0; vhi < 8; vhi++) {
        int off = vhi * 128 + lane * 4;
        int s = vhi * 4;
        {
            float4 a, b;
            unpk(val[(s + 0) * 2 + 0], a.x, b.x);
            unpk(val[(s + 1) * 2 + 0], a.y, b.y);
            unpk(val[(s + 2) * 2 + 0], a.z, b.z);
            unpk(val[(s + 3) * 2 + 0], a.w, b.w);
            *(float4*)(yr0 + off) = a;
            *(float4*)(yr1 + off) = b;
        }
        cfence();
        {
            float4 c, d;
            unpk(val[(s + 0) * 2 + 1], c.x, d.x);
            unpk(val[(s + 1) * 2 + 1], c.y, d.y);
            unpk(val[(s + 2) * 2 + 1], c.z, d.z);
            unpk(val[(s + 3) * 2 + 1], c.w, d.w);
            *(float4*)(yr2 + off) = c;
            *(float4*)(yr3 + off) = d;
        }
        cfence();
    }
}

extern "C" void kernel_launch(void* const* d_in, const int* in_sizes, int n_in,
                              void* d_out, int out_size) {
    const float* X     = (const float*)d_in[0];
    const float* bp    = (const float*)d_in[1];
    const float* bias  = (const float*)d_in[2];
    const float* slope = (const float*)d_in[3];
    const float* scale = (const float*)d_in[4];
    float* Y = (float*)d_out;

    prep_all<<<(BT_ELEMS + T0_ELEMS + QT_ELEMS + 255) / 256, 256>>>(bp, bias, slope, scale);
    // 4 rows per warp, 4 warps per CTA -> 16 rows per CTA; 3 CTAs/SM target
    net_kernel<<<BATCH / 16, 128>>>(X, Y);
}

// round 8
// speedup vs baseline: 3.7118x; 3.7118x over previous
#include <cuda_runtime.h>
#include <cstdint>

#define WIDTH  1024
#define HALF   512
#define DEPTH  8
#define BDEPTH 10
#define BATCH  65536

typedef unsigned long long ull;

// Geometry:
//   lane = p bits [6:2]  (32 lanes)
//   slot v (0..31): p = ((v>>2)<<7) | (lane<<2) | (v&3)   -> v bits = p bits {1,0,9,8,7}
//   thread holds val[v*2+h]: h=0 rows(0,1), h=1 rows(2,3) packed in f32x2.
// Steps t (bit b = 9-t): t=0,1,2 reg (v bits 4,3,2); t=3..7 lane (lane bits 4..0);
//                        t=8,9 reg (v bits 1,0).
//
// g_bt (steps t=1..9): 256 float4 per step, LDG.128:
//   reg step:  entry[e*32 + lane], e=0..7:  (c[pi=2e], s[2e], c[2e+1], s[2e+1])
//   lane step: entry[e*16 + lp],  e=0..15: (c[v=2e],  s[2e], c[2e+1], s[2e+1])
// g_t0 (step t=0, scale-folded): entry[L*512 + pi*32 + lane] = (a, b, -g, d)
//   n0 = a*x0 + b*x1 ; n1 = (-g)*x0 + d*x1 with a=c*sc0, b=s*sc1, g=s*sc0, d=c*sc1
//   (sc = previous layer's quintic scale; sc=1 for layer 0).
__device__ float4 g_bt[DEPTH * BDEPTH * 256];
__device__ float4 g_t0[DEPTH * 512];
// quintic (scale folded out): entry[act*512 + e*32 + lane] = (m_v0, nb_v0, m_v1, nb_v1)
__device__ float4 g_qt[(DEPTH - 1) * 512];

// ---------- f32x2 helpers ----------
__device__ __forceinline__ ull pk(float lo, float hi) {
    ull r;
    asm("mov.b64 %0, {%1, %2};" : "=l"(r) : "r"(__float_as_uint(lo)), "r"(__float_as_uint(hi)));
    return r;
}
__device__ __forceinline__ void unpk(ull v, float& lo, float& hi) {
    unsigned a, b;
    asm("mov.b64 {%0, %1}, %2;" : "=r"(a), "=r"(b) : "l"(v));
    lo = __uint_as_float(a);
    hi = __uint_as_float(b);
}
__device__ __forceinline__ ull f2mul(ull a, ull b) {
    ull r;
    asm("mul.rn.f32x2 %0, %1, %2;" : "=l"(r) : "l"(a), "l"(b));
    return r;
}
__device__ __forceinline__ ull f2fma(ull a, ull b, ull c) {
    ull r;
    asm("fma.rn.f32x2 %0, %1, %2, %3;" : "=l"(r) : "l"(a), "l"(b), "l"(c));
    return r;
}
__device__ __forceinline__ void cfence() { asm volatile("" ::: "memory"); }

// ---------- prep ----------
#define BT_ELEMS (DEPTH * BDEPTH * 256)
#define T0_ELEMS (DEPTH * 512)
#define QT_ELEMS ((DEPTH - 1) * 512)

__device__ __forceinline__ float theta_of(const float* bp, int layer, int t, int p0) {
    int j = 0;
#pragma unroll
    for (int k = 0; k < 9; k++) {
        int src = ((k - t) % 10 + 10) % 10;
        j |= ((p0 >> src) & 1) << k;
    }
    return bp[layer * (HALF * BDEPTH) + j * BDEPTH + t];
}

__global__ void prep_all(const float* __restrict__ bp,
                         const float* __restrict__ bias,
                         const float* __restrict__ slope,
                         const float* __restrict__ scale) {
    int e0 = blockIdx.x * blockDim.x + threadIdx.x;
    if (e0 < BT_ELEMS) {
        int T = e0 >> 8;
        int idx = e0 & 255;
        int layer = T / BDEPTH;
        int t = T % BDEPTH;
        if (t == 0) return;  // t=0 handled via g_t0
        int b = 9 - t;

        float4 out;
        if (b >= 7 || b <= 1) {
            int sbit = (b >= 7) ? (b - 5) : b;
            int m = 1 << sbit;
            int e = idx >> 5;
            int lane = idx & 31;
            float cs[4];
#pragma unroll
            for (int k = 0; k < 2; k++) {
                int pi = 2 * e + k;
                int v0 = (pi & (m - 1)) | ((pi & ~(m - 1)) << 1);
                int p0 = ((v0 >> 2) << 7) | (lane << 2) | (v0 & 3);
                float th = theta_of(bp, layer, t, p0);
                float s, c;
                sincosf(th, &s, &c);
                cs[2 * k] = c;
                cs[2 * k + 1] = s;
            }
            out = make_float4(cs[0], cs[1], cs[2], cs[3]);
        } else {
            int lm = 1 << (b - 2);
            int e = idx >> 4;
            int lp = idx & 15;
            int l0 = (lp & (lm - 1)) | ((lp & ~(lm - 1)) << 1);
            float cs[4];
#pragma unroll
            for (int k = 0; k < 2; k++) {
                int v = 2 * e + k;
                int p0 = ((v >> 2) << 7) | (l0 << 2) | (v & 3);
                float th = theta_of(bp, layer, t, p0);
                float s, c;
                sincosf(th, &s, &c);
                cs[2 * k] = c;
                cs[2 * k + 1] = s;
            }
            out = make_float4(cs[0], cs[1], cs[2], cs[3]);
        }
        g_bt[e0] = out;
    } else if (e0 < BT_ELEMS + T0_ELEMS) {
        int q = e0 - BT_ELEMS;
        int layer = q >> 9;
        int idx = q & 511;
        int pi = idx >> 5;          // pair 0..15: v0 = pi, v1 = pi|16 (M=16)
        int lane = idx & 31;
        int v0 = pi, v1 = pi | 16;
        int p0 = ((v0 >> 2) << 7) | (lane << 2) | (v0 & 3);
        int p1 = ((v1 >> 2) << 7) | (lane << 2) | (v1 & 3);
        float th = theta_of(bp, layer, 0, p0);
        float s, c;
        sincosf(th, &s, &c);
        float sc0 = 1.0f, sc1 = 1.0f;
        if (layer > 0) {
            sc0 = scale[(layer - 1) * WIDTH + p0];
            sc1 = scale[(layer - 1) * WIDTH + p1];
        }
        g_t0[q] = make_float4(c * sc0, s * sc1, -s * sc0, c * sc1);
    } else if (e0 < BT_ELEMS + T0_ELEMS + QT_ELEMS) {
        int q = e0 - BT_ELEMS - T0_ELEMS;
        int act = q >> 9;
        int idx = q & 511;
        int e = idx >> 5;           // v0 = 2e, v1 = 2e+1
        int l = idx & 31;
        float mv[2], nbv[2];
#pragma unroll
        for (int k = 0; k < 2; k++) {
            int v = 2 * e + k;
            int p0 = ((v >> 2) << 7) | (l << 2) | (v & 3);
            float bi = bias[act * WIDTH + p0];
            float sl = slope[act * WIDTH + p0];
            float sc = scale[act * WIDTH + p0];
            mv[k] = sl / sc;
            nbv[k] = -bi / sc;
        }
        g_qt[q] = make_float4(mv[0], nbv[0], mv[1], nbv[1]);
    }
}

// ---------- main kernel ----------

__device__ __forceinline__ void bfly_pair(ull (&val)[64], int v0, int v1, float c, float s) {
    ull c2 = pk(c, c);
    ull s2 = pk(s, s);
    ull ns2 = s2 ^ 0x8000000080000000ULL;
#pragma unroll
    for (int h = 0; h < 2; h++) {
        ull x0 = val[v0 * 2 + h];
        ull x1 = val[v1 * 2 + h];
        val[v0 * 2 + h] = f2fma(c2, x0, f2mul(s2, x1));   // n0 =  c*x0 + s*x1
        val[v1 * 2 + h] = f2fma(c2, x1, f2mul(ns2, x0));  // n1 =  c*x1 - s*x0
    }
}

// t=0 with folded scale: n0 = a*x0 + b*x1 ; n1 = g*x0 + d*x1 (g pre-negated)
__device__ __forceinline__ void t0_step(ull (&val)[64], int lane, const float4* __restrict__ t0t) {
#pragma unroll
    for (int pi = 0; pi < 16; pi++) {
        float4 q = __ldg(t0t + pi * 32 + lane);
        ull a2 = pk(q.x, q.x);
        ull b2 = pk(q.y, q.y);
        ull g2 = pk(q.z, q.z);
        ull d2 = pk(q.w, q.w);
        const int v0 = pi, v1 = pi | 16;
#pragma unroll
        for (int h = 0; h < 2; h++) {
            ull x0 = val[v0 * 2 + h];
            ull x1 = val[v1 * 2 + h];
            val[v0 * 2 + h] = f2fma(a2, x0, f2mul(b2, x1));
            val[v1 * 2 + h] = f2fma(g2, x0, f2mul(d2, x1));
        }
        if ((pi & 3) == 3) cfence();
    }
}

template <int M>
__device__ __forceinline__ void reg_step(ull (&val)[64], int lane, const float4* __restrict__ bt) {
#pragma unroll
    for (int e = 0; e < 8; e++) {
        float4 q = __ldg(bt + e * 32 + lane);
        {
            const int pi = 2 * e;
            const int v0 = (pi & (M - 1)) | ((pi & ~(M - 1)) << 1);
            bfly_pair(val, v0, v0 | M, q.x, q.y);
        }
        {
            const int pi = 2 * e + 1;
            const int v0 = (pi & (M - 1)) | ((pi & ~(M - 1)) << 1);
            bfly_pair(val, v0, v0 | M, q.z, q.w);
        }
        if ((e & 3) == 3) cfence();
    }
}

template <int LM>
__device__ __forceinline__ void lane_step(ull (&val)[64], int lane, const float4* __restrict__ bt) {
    const ull smask = (lane & LM) ? 0x8000000080000000ULL : 0ULL;
    const int lp = (lane & (LM - 1)) | ((lane >> 1) & ~(LM - 1));
#pragma unroll
    for (int e = 0; e < 16; e++) {
        float4 q = __ldg(bt + e * 16 + lp);
#pragma unroll
        for (int k = 0; k < 2; k++) {
            const int v = 2 * e + k;
            float c = k ? q.z : q.x;
            float s = k ? q.w : q.y;
            ull c2 = pk(c, c);
            ull s2 = pk(s, s) ^ smask;
#pragma unroll
            for (int h = 0; h < 2; h++) {
                ull x = val[v * 2 + h];
                ull xp = __shfl_xor_sync(0xffffffffu, x, LM);
                val[v * 2 + h] = f2fma(c2, x, f2mul(s2, xp));
            }
        }
        if ((e & 3) == 3) cfence();
    }
}

// quintic WITHOUT trailing scale (folded into next layer's t0)
__device__ __forceinline__ void quintic(ull (&val)[64], int lane, int act) {
    const float4* __restrict__ qt = g_qt + act * 512;
    const ull C1875 = 0x3FF000003FF00000ULL;  // (1.875, 1.875)
    const ull CM125 = 0xBFA00000BFA00000ULL;  // (-1.25, -1.25)
    const ull C0375 = 0x3EC000003EC00000ULL;  // (0.375, 0.375)
#pragma unroll
    for (int e = 0; e < 16; e++) {
        float4 q = __ldg(qt + e * 32 + lane);
#pragma unroll
        for (int k = 0; k < 2; k++) {
            const int v = 2 * e + k;
            ull m2 = pk(k ? q.z : q.x, k ? q.z : q.x);
            ull nb2 = pk(k ? q.w : q.y, k ? q.w : q.y);
#pragma unroll
            for (int h = 0; h < 2; h++) {
                ull u = f2fma(val[v * 2 + h], m2, nb2);
                float lo, hi;
                unpk(u, lo, hi);
                lo = fminf(fmaxf(lo, -1.0f), 1.0f);
                hi = fminf(fmaxf(hi, -1.0f), 1.0f);
                u = pk(lo, hi);
                ull u2 = f2mul(u, u);
                ull p = f2fma(u2, C0375, CM125);
                p = f2fma(u2, p, C1875);
                val[v * 2 + h] = f2mul(u, p);
            }
        }
        if ((e & 3) == 3) cfence();
    }
}

__global__ void __launch_bounds__(128)
net_kernel(const float* __restrict__ X, float* __restrict__ Y) {
    const int lane = threadIdx.x & 31;
    const int w = blockIdx.x * 4 + (threadIdx.x >> 5);
    const long long row0 = (long long)w * 4;
    const float* __restrict__ xr0 = X + row0 * WIDTH;
    const float* __restrict__ xr1 = xr0 + WIDTH;
    const float* __restrict__ xr2 = xr1 + WIDTH;
    const float* __restrict__ xr3 = xr2 + WIDTH;

    ull val[64];

    // load: 4 rows; val[v*2+h]: h=0 -> (row0,row1), h=1 -> (row2,row3)
#pragma unroll
    for (int vhi = 0; vhi < 8; vhi++) {
        int off = vhi * 128 + lane * 4;
        int s = vhi * 4;
        {
            float4 a = *(const float4*)(xr0 + off);
            float4 b = *(const float4*)(xr1 + off);
            val[(s + 0) * 2 + 0] = pk(a.x, b.x);
            val[(s + 1) * 2 + 0] = pk(a.y, b.y);
            val[(s + 2) * 2 + 0] = pk(a.z, b.z);
            val[(s + 3) * 2 + 0] = pk(a.w, b.w);
        }
        cfence();
        {
            float4 c = *(const float4*)(xr2 + off);
            float4 d = *(const float4*)(xr3 + off);
            val[(s + 0) * 2 + 1] = pk(c.x, d.x);
            val[(s + 1) * 2 + 1] = pk(c.y, d.y);
            val[(s + 2) * 2 + 1] = pk(c.z, d.z);
            val[(s + 3) * 2 + 1] = pk(c.w, d.w);
        }
        cfence();
    }

#pragma unroll 1
    for (int layer = 0; layer < DEPTH; layer++) {
        const float4* __restrict__ bt = g_bt + layer * (BDEPTH * 256);
        t0_step(val, lane, g_t0 + layer * 512);  // t=0: p bit 9, scale-folded
        reg_step<8>(val, lane, bt + 1 * 256);    // t=1: p bit 8 (v bit 3)
        reg_step<4>(val, lane, bt + 2 * 256);    // t=2: p bit 7 (v bit 2)
        lane_step<16>(val, lane, bt + 3 * 256);  // t=3: p bit 6 (lane bit 4)
        lane_step<8>(val, lane, bt + 4 * 256);   // t=4: p bit 5
        lane_step<4>(val, lane, bt + 5 * 256);   // t=5: p bit 4
        lane_step<2>(val, lane, bt + 6 * 256);   // t=6: p bit 3
        lane_step<1>(val, lane, bt + 7 * 256);   // t=7: p bit 2 (lane bit 0)
        reg_step<2>(val, lane, bt + 8 * 256);    // t=8: p bit 1 (v bit 1)
        reg_step<1>(val, lane, bt + 9 * 256);    // t=9: p bit 0 (v bit 0)
        if (layer < DEPTH - 1) quintic(val, lane, layer);
    }

    // store (net permutation over 10 steps per layer is identity)
    float* __restrict__ yr0 = Y + row0 * WIDTH;
    float* __restrict__ yr1 = yr0 + WIDTH;
    float* __restrict__ yr2 = yr1 + WIDTH;
    float* __restrict__ yr3 = yr2 + WIDTH;
#pragma unroll
    for (int vhi = 0; vhi < 8; vhi++) {
        int off = vhi * 128 + lane * 4;
        int s = vhi * 4;
        {
            float4 a, b;
            unpk(val[(s + 0) * 2 + 0], a.x, b.x);
            unpk(val[(s + 1) * 2 + 0], a.y, b.y);
            unpk(val[(s + 2) * 2 + 0], a.z, b.z);
            unpk(val[(s + 3) * 2 + 0], a.w, b.w);
            *(float4*)(yr0 + off) = a;
            *(float4*)(yr1 + off) = b;
        }
        cfence();
        {
            float4 c, d;
            unpk(val[(s + 0) * 2 + 1], c.x, d.x);
            unpk(val[(s + 1) * 2 + 1], c.y, d.y);
            unpk(val[(s + 2) * 2 + 1], c.z, d.z);
            unpk(val[(s + 3) * 2 + 1], c.w, d.w);
            *(float4*)(yr2 + off) = c;
            *(float4*)(yr3 + off) = d;
        }
        cfence();
    }
}

extern "C" void kernel_launch(void* const* d_in, const int* in_sizes, int n_in,
                              void* d_out, int out_size) {
    const float* X     = (const float*)d_in[0];
    const float* bp    = (const float*)d_in[1];
    const float* bias  = (const float*)d_in[2];
    const float* slope = (const float*)d_in[3];
    const float* scale = (const float*)d_in[4];
    float* Y = (float*)d_out;

    prep_all<<<(BT_ELEMS + T0_ELEMS + QT_ELEMS + 255) / 256, 256>>>(bp, bias, slope, scale);
    // 4 rows per warp, 4 warps per CTA -> 16 rows per CTA; ~242 regs, 2 CTAs/SM
    net_kernel<<<BATCH / 16, 128>>>(X, Y);
}